// round 13
// baseline (speedup 1.0000x reference)
#include <cuda_runtime.h>
#include <cuda_bf16.h>
#include <math.h>

// Problem constants (fixed shapes from reference setup_inputs)
#define WW 1920
#define HH 1080
#define CC 3
#define BB 4
#define HWN (HH * WW)            // 2,073,600
#define NN  (BB * HWN)           // 8,294,400
#define MOTION_TH_I 25           // 0.25 * D_SCALE_INT
#define TPB 192                  // threads per block; 2 px/thread -> 384 px; 1920/384 = 5

// Scratch (allocation-free rule: __device__ globals).
// INVARIANT: both buffers are all-zero at kernel_launch entry. They are
// zero-initialized at module load, and normalize_kernel re-zeroes them after
// consuming them, restoring the invariant for the next (identical) call.
__device__ int    g_dbuf[NN];
__device__ float4 g_acc[NN];     // [c0, c1, c2, weight] per destination pixel

struct Corners {
    int   valid;      // 0/1
    int   d;          // depth int
    float k[4];       // nw, ne, sw, se
    int   idx[4];     // flat pixel index within batch image (y*W + x), clipped
};

__device__ __forceinline__ Corners compute_corners(float fx, float fy, int x, int y)
{
    Corners c;
    float xd = (float)x + fx;
    float yd = (float)y + fy;

    float magsq = fx * fx + fy * fy;
    c.d = (int)(100.0f * sqrtf(magsq));

    int xf = (int)floorf(xd);
    int yf = (int)floorf(yd);
    int xc = xf + 1;
    int yc = yf + 1;

    c.valid = (xf >= 0) & (xc <= WW) & (yf >= 0) & (yc <= HH);

    float xf_f = (float)xf, yf_f = (float)yf;
    float xc_f = (float)xc, yc_f = (float)yc;
    float wx1 = xc_f - xd;
    float wx0 = xd - xf_f;
    float wy1 = yc_f - yd;
    float wy0 = yd - yf_f;
    c.k[0] = wx1 * wy1;  // nw
    c.k[1] = wx0 * wy1;  // ne
    c.k[2] = wx1 * wy0;  // sw
    c.k[3] = wx0 * wy0;  // se

    int xfc = min(max(xf, 0), WW - 1);
    int yfc = min(max(yf, 0), HH - 1);
    int xcc = min(max(xc, 0), WW - 1);
    int ycc = min(max(yc, 0), HH - 1);
    c.idx[0] = yfc * WW + xfc;
    c.idx[1] = yfc * WW + xcc;
    c.idx[2] = ycc * WW + xfc;
    c.idx[3] = ycc * WW + xcc;
    return c;
}

__device__ __forceinline__ void red_add_v4(float4* addr, float a, float b, float cc, float dd)
{
    asm volatile("red.global.add.v4.f32 [%0], {%1, %2, %3, %4};"
                 :: "l"(addr), "f"(a), "f"(b), "f"(cc), "f"(dd)
                 : "memory");
}

// grid: (5, 1080), block: 192 -> 2 px/thread, x covers [0,1920) exactly.
__global__ void __launch_bounds__(TPB) scatter_max_kernel(const float4* __restrict__ flow2,
                                                          int* __restrict__ dbuf)
{
    int t = blockIdx.x * TPB + threadIdx.x;   // pair index in row [0, 960)
    int y = blockIdx.y;
    int x0 = t * 2;

    float4 f2 = flow2[y * (WW / 2) + t];
    Corners c0 = compute_corners(f2.x, f2.y, x0,     y);
    Corners c1 = compute_corners(f2.z, f2.w, x0 + 1, y);

    #pragma unroll
    for (int j = 0; j < 4; j++)
        if (c0.valid && c0.k[j] >= 0.25f) atomicMax(&dbuf[c0.idx[j]], c0.d);
    #pragma unroll
    for (int j = 0; j < 4; j++)
        if (c1.valid && c1.k[j] >= 0.25f) atomicMax(&dbuf[c1.idx[j]], c1.d);
}

// grid: (5, 1080), block: 192 -> 2 px/thread. Gathers batched before REDs for MLP.
__global__ void __launch_bounds__(TPB) splat_kernel(const float* __restrict__ im0,
                                                    const float4* __restrict__ flow2,
                                                    const int* __restrict__ dbuf,
                                                    float4* __restrict__ acc)
{
    int t = blockIdx.x * TPB + threadIdx.x;
    int y = blockIdx.y;
    int x0 = t * 2;
    int p = y * WW + x0;

    float4 f2 = flow2[y * (WW / 2) + t];
    Corners c0 = compute_corners(f2.x, f2.y, x0,     y);
    Corners c1 = compute_corners(f2.z, f2.w, x0 + 1, y);

    // Batched predicated gathers (independent; issue together -> MLP ~3.2)
    int g0[4], g1[4];
    #pragma unroll
    for (int j = 0; j < 4; j++)
        g0[j] = (c0.valid && c0.k[j] >= 0.25f) ? __ldg(&dbuf[c0.idx[j]]) : 0x7FFFFFFF;
    #pragma unroll
    for (int j = 0; j < 4; j++)
        g1[j] = (c1.valid && c1.k[j] >= 0.25f) ? __ldg(&dbuf[c1.idx[j]]) : 0x7FFFFFFF;

    // Coalesced source reads (read-once: streaming/evict-first)
    float2 v0 = __ldcs((const float2*)&im0[0 * HWN + p]);
    float2 v1 = __ldcs((const float2*)&im0[1 * HWN + p]);
    float2 v2 = __ldcs((const float2*)&im0[2 * HWN + p]);

    // Depth test alone gates the RED: masked lanes hold INT_MAX (d <= ~24000, no overflow).
    #pragma unroll
    for (int j = 0; j < 4; j++) {
        if (g0[j] - c0.d <= MOTION_TH_I) {
            float k = c0.k[j];
            red_add_v4(&acc[c0.idx[j]], v0.x * k, v1.x * k, v2.x * k, k);
        }
    }
    #pragma unroll
    for (int j = 0; j < 4; j++) {
        if (g1[j] - c1.d <= MOTION_TH_I) {
            float k = c1.k[j];
            red_add_v4(&acc[c1.idx[j]], v0.y * k, v1.y * k, v2.y * k, k);
        }
    }
}

// 4 pixels per thread. Produces output AND restores the zero-invariant on
// dbuf/acc for the next call (replaces the front-of-chain zero pass).
__global__ void __launch_bounds__(128) normalize_kernel(float4* __restrict__ acc,
                                                        int* __restrict__ dbuf,
                                                        float* __restrict__ out)
{
    int q = blockIdx.x * 128 + threadIdx.x;
    if (q >= WW / 4) return;
    int y = blockIdx.y;
    int p = y * WW + q * 4;

    float4 a0 = __ldcs(&acc[p + 0]);
    float4 a1 = __ldcs(&acc[p + 1]);
    float4 a2 = __ldcs(&acc[p + 2]);
    float4 a3 = __ldcs(&acc[p + 3]);

    float inv0 = 1.0f / fmaxf(a0.w * (1.0f / 3.0f), 1e-5f);
    float inv1 = 1.0f / fmaxf(a1.w * (1.0f / 3.0f), 1e-5f);
    float inv2 = 1.0f / fmaxf(a2.w * (1.0f / 3.0f), 1e-5f);
    float inv3 = 1.0f / fmaxf(a3.w * (1.0f / 3.0f), 1e-5f);

    __stcs((float4*)&out[0 * HWN + p],
           make_float4(a0.x * inv0, a1.x * inv1, a2.x * inv2, a3.x * inv3));
    __stcs((float4*)&out[1 * HWN + p],
           make_float4(a0.y * inv0, a1.y * inv1, a2.y * inv2, a3.y * inv3));
    __stcs((float4*)&out[2 * HWN + p],
           make_float4(a0.z * inv0, a1.z * inv1, a2.z * inv2, a3.z * inv3));

    // Cleanup: re-zero scratch for the next call (streaming, evict-first).
    float4 z = make_float4(0.f, 0.f, 0.f, 0.f);
    __stcs(&acc[p + 0], z);
    __stcs(&acc[p + 1], z);
    __stcs(&acc[p + 2], z);
    __stcs(&acc[p + 3], z);
    __stcs((int4*)&dbuf[p], make_int4(0, 0, 0, 0));
}

extern "C" void kernel_launch(void* const* d_in, const int* in_sizes, int n_in,
                              void* d_out, int out_size)
{
    const float*  im0  = (const float*)d_in[0];
    const float*  flow = (const float*)d_in[1];
    float* out = (float*)d_out;

    // One-time creation of side streams/events (no device memory involved).
    // Exactly 4 streams total (clean graph teardown).
    static cudaStream_t s_side[BB - 1];
    static cudaEvent_t  e_fork;
    static cudaEvent_t  e_join[BB - 1];
    static bool s_init = [](){
        for (int i = 0; i < BB - 1; i++)
            cudaStreamCreateWithFlags(&s_side[i], cudaStreamNonBlocking);
        cudaEventCreateWithFlags(&e_fork, cudaEventDisableTiming);
        for (int i = 0; i < BB - 1; i++)
            cudaEventCreateWithFlags(&e_join[i], cudaEventDisableTiming);
        return true;
    }();
    (void)s_init;

    int*    dbuf = nullptr;
    float4* acc  = nullptr;
    {
        void *pd = nullptr, *pa = nullptr;
        cudaGetSymbolAddress(&pd, g_dbuf);
        cudaGetSymbolAddress(&pa, g_acc);
        dbuf = (int*)pd;
        acc  = (float4*)pa;
    }

    cudaStream_t main_s = 0;  // capture stream (legacy default)
    cudaEventRecord(e_fork, main_s);

    dim3 blk(TPB, 1, 1);
    dim3 grd(WW / 2 / TPB, HH, 1);       // 5 x 1080
    dim3 blkn(128, 1, 1);
    dim3 grdn(WW / 4 / 128 + 1, HH, 1);  // 4 x 1080

    for (int b = 0; b < BB; b++) {
        cudaStream_t st = (b == 0) ? main_s : s_side[b - 1];
        if (b != 0) cudaStreamWaitEvent(st, e_fork, 0);

        const float4* flow_b = (const float4*)(flow + (size_t)b * HWN * 2);
        const float*  im0_b  = im0 + (size_t)b * CC * HWN;
        float*        out_b  = out + (size_t)b * CC * HWN;
        int*          dbuf_b = dbuf + (size_t)b * HWN;
        float4*       acc_b  = acc  + (size_t)b * HWN;

        scatter_max_kernel<<<grd, blk, 0, st>>>(flow_b, dbuf_b);
        splat_kernel<<<grd, blk, 0, st>>>(im0_b, flow_b, dbuf_b, acc_b);
        normalize_kernel<<<grdn, blkn, 0, st>>>(acc_b, dbuf_b, out_b);

        if (b != 0) cudaEventRecord(e_join[b - 1], st);
    }
    for (int i = 0; i < BB - 1; i++)
        cudaStreamWaitEvent(main_s, e_join[i], 0);
}

// round 16
// speedup vs baseline: 1.0106x; 1.0106x over previous
#include <cuda_runtime.h>
#include <cuda_bf16.h>
#include <math.h>

// Problem constants (fixed shapes from reference setup_inputs)
#define WW 1920
#define HH 1080
#define CC 3
#define BB 4
#define HWN (HH * WW)            // 2,073,600
#define NN  (BB * HWN)           // 8,294,400
#define MOTION_TH_I 25           // 0.25 * D_SCALE_INT
#define TPB 192                  // threads per block; 2 px/thread -> 384 px; 1920/384 = 5

// Scratch (allocation-free rule: __device__ globals)
__device__ int    g_dbuf[NN];
__device__ float4 g_acc[NN];     // [c0, c1, c2, weight] per destination pixel

struct Corners {
    int   valid;      // 0/1
    int   d;          // depth int
    float k[4];       // nw, ne, sw, se
    int   idx[4];     // flat pixel index within batch image (y*W + x), clipped
};

__device__ __forceinline__ Corners compute_corners(float fx, float fy, int x, int y)
{
    Corners c;
    float xd = (float)x + fx;
    float yd = (float)y + fy;

    float magsq = fx * fx + fy * fy;
    c.d = (int)(100.0f * sqrtf(magsq));

    int xf = (int)floorf(xd);
    int yf = (int)floorf(yd);
    int xc = xf + 1;
    int yc = yf + 1;

    c.valid = (xf >= 0) & (xc <= WW) & (yf >= 0) & (yc <= HH);

    float xf_f = (float)xf, yf_f = (float)yf;
    float xc_f = (float)xc, yc_f = (float)yc;
    float wx1 = xc_f - xd;
    float wx0 = xd - xf_f;
    float wy1 = yc_f - yd;
    float wy0 = yd - yf_f;
    c.k[0] = wx1 * wy1;  // nw
    c.k[1] = wx0 * wy1;  // ne
    c.k[2] = wx1 * wy0;  // sw
    c.k[3] = wx0 * wy0;  // se

    int xfc = min(max(xf, 0), WW - 1);
    int yfc = min(max(yf, 0), HH - 1);
    int xcc = min(max(xc, 0), WW - 1);
    int ycc = min(max(yc, 0), HH - 1);
    c.idx[0] = yfc * WW + xfc;
    c.idx[1] = yfc * WW + xcc;
    c.idx[2] = ycc * WW + xfc;
    c.idx[3] = ycc * WW + xcc;
    return c;
}

__device__ __forceinline__ void red_add_v4(float4* addr, float a, float b, float cc, float dd)
{
    asm volatile("red.global.add.v4.f32 [%0], {%1, %2, %3, %4};"
                 :: "l"(addr), "f"(a), "f"(b), "f"(cc), "f"(dd)
                 : "memory");
}

// Zero dbuf slice only (scatter's sole dependency): 2MB -> ~2us.
#define DB4 (HWN / 4)            // 518,400 int4
__global__ void __launch_bounds__(256) zero_dbuf_kernel(int4* __restrict__ dbuf4)
{
    int i = blockIdx.x * 256 + threadIdx.x;
    if (i < DB4) __stcs(&dbuf4[i], make_int4(0, 0, 0, 0));
}

// Zero acc slice (splat's dependency); runs between scatter and splat,
// hidden under other streams' atomic phases. Evict-first: no L2 pollution.
__global__ void __launch_bounds__(256) zero_acc_kernel(float4* __restrict__ acc)
{
    int i = blockIdx.x * 256 + threadIdx.x;
    if (i < HWN) __stcs(&acc[i], make_float4(0.f, 0.f, 0.f, 0.f));
}

// grid: (5, 1080), block: 192 -> 2 px/thread, x covers [0,1920) exactly.
__global__ void __launch_bounds__(TPB) scatter_max_kernel(const float4* __restrict__ flow2,
                                                          int* __restrict__ dbuf)
{
    int t = blockIdx.x * TPB + threadIdx.x;   // pair index in row [0, 960)
    int y = blockIdx.y;
    int x0 = t * 2;

    float4 f2 = flow2[y * (WW / 2) + t];
    Corners c0 = compute_corners(f2.x, f2.y, x0,     y);
    Corners c1 = compute_corners(f2.z, f2.w, x0 + 1, y);

    #pragma unroll
    for (int j = 0; j < 4; j++)
        if (c0.valid && c0.k[j] >= 0.25f) atomicMax(&dbuf[c0.idx[j]], c0.d);
    #pragma unroll
    for (int j = 0; j < 4; j++)
        if (c1.valid && c1.k[j] >= 0.25f) atomicMax(&dbuf[c1.idx[j]], c1.d);
}

// grid: (5, 1080), block: 192 -> 2 px/thread. Gathers batched before REDs for MLP.
__global__ void __launch_bounds__(TPB) splat_kernel(const float* __restrict__ im0,
                                                    const float4* __restrict__ flow2,
                                                    const int* __restrict__ dbuf,
                                                    float4* __restrict__ acc)
{
    int t = blockIdx.x * TPB + threadIdx.x;
    int y = blockIdx.y;
    int x0 = t * 2;
    int p = y * WW + x0;

    float4 f2 = flow2[y * (WW / 2) + t];
    Corners c0 = compute_corners(f2.x, f2.y, x0,     y);
    Corners c1 = compute_corners(f2.z, f2.w, x0 + 1, y);

    // Batched predicated gathers (independent; issue together -> MLP ~3.2)
    int g0[4], g1[4];
    #pragma unroll
    for (int j = 0; j < 4; j++)
        g0[j] = (c0.valid && c0.k[j] >= 0.25f) ? __ldg(&dbuf[c0.idx[j]]) : 0x7FFFFFFF;
    #pragma unroll
    for (int j = 0; j < 4; j++)
        g1[j] = (c1.valid && c1.k[j] >= 0.25f) ? __ldg(&dbuf[c1.idx[j]]) : 0x7FFFFFFF;

    // Coalesced source reads (read-once: streaming/evict-first)
    float2 v0 = __ldcs((const float2*)&im0[0 * HWN + p]);
    float2 v1 = __ldcs((const float2*)&im0[1 * HWN + p]);
    float2 v2 = __ldcs((const float2*)&im0[2 * HWN + p]);

    // Depth test alone gates the RED: masked lanes hold INT_MAX (d <= ~24000, no overflow).
    #pragma unroll
    for (int j = 0; j < 4; j++) {
        if (g0[j] - c0.d <= MOTION_TH_I) {
            float k = c0.k[j];
            red_add_v4(&acc[c0.idx[j]], v0.x * k, v1.x * k, v2.x * k, k);
        }
    }
    #pragma unroll
    for (int j = 0; j < 4; j++) {
        if (g1[j] - c1.d <= MOTION_TH_I) {
            float k = c1.k[j];
            red_add_v4(&acc[c1.idx[j]], v0.y * k, v1.y * k, v2.y * k, k);
        }
    }
}

// 4 pixels per thread, vectorized, streaming loads/stores. grid: (4, 1080), block: 128
__global__ void __launch_bounds__(128) normalize_kernel(const float4* __restrict__ acc,
                                                        float* __restrict__ out)
{
    int q = blockIdx.x * 128 + threadIdx.x;
    if (q >= WW / 4) return;
    int y = blockIdx.y;
    int p = y * WW + q * 4;

    float4 a0 = __ldcs(&acc[p + 0]);
    float4 a1 = __ldcs(&acc[p + 1]);
    float4 a2 = __ldcs(&acc[p + 2]);
    float4 a3 = __ldcs(&acc[p + 3]);

    float inv0 = 1.0f / fmaxf(a0.w * (1.0f / 3.0f), 1e-5f);
    float inv1 = 1.0f / fmaxf(a1.w * (1.0f / 3.0f), 1e-5f);
    float inv2 = 1.0f / fmaxf(a2.w * (1.0f / 3.0f), 1e-5f);
    float inv3 = 1.0f / fmaxf(a3.w * (1.0f / 3.0f), 1e-5f);

    __stcs((float4*)&out[0 * HWN + p],
           make_float4(a0.x * inv0, a1.x * inv1, a2.x * inv2, a3.x * inv3));
    __stcs((float4*)&out[1 * HWN + p],
           make_float4(a0.y * inv0, a1.y * inv1, a2.y * inv2, a3.y * inv3));
    __stcs((float4*)&out[2 * HWN + p],
           make_float4(a0.z * inv0, a1.z * inv1, a2.z * inv2, a3.z * inv3));
}

extern "C" void kernel_launch(void* const* d_in, const int* in_sizes, int n_in,
                              void* d_out, int out_size)
{
    const float*  im0  = (const float*)d_in[0];
    const float*  flow = (const float*)d_in[1];
    float* out = (float*)d_out;

    // One-time creation of side streams/events (no device memory involved).
    // Exactly 4 streams total (clean graph teardown).
    static cudaStream_t s_side[BB - 1];
    static cudaEvent_t  e_fork;
    static cudaEvent_t  e_join[BB - 1];
    static bool s_init = [](){
        for (int i = 0; i < BB - 1; i++)
            cudaStreamCreateWithFlags(&s_side[i], cudaStreamNonBlocking);
        cudaEventCreateWithFlags(&e_fork, cudaEventDisableTiming);
        for (int i = 0; i < BB - 1; i++)
            cudaEventCreateWithFlags(&e_join[i], cudaEventDisableTiming);
        return true;
    }();
    (void)s_init;

    int*    dbuf = nullptr;
    float4* acc  = nullptr;
    {
        void *pd = nullptr, *pa = nullptr;
        cudaGetSymbolAddress(&pd, g_dbuf);
        cudaGetSymbolAddress(&pa, g_acc);
        dbuf = (int*)pd;
        acc  = (float4*)pa;
    }

    cudaStream_t main_s = 0;  // capture stream (legacy default)
    cudaEventRecord(e_fork, main_s);

    dim3 blk(TPB, 1, 1);
    dim3 grd(WW / 2 / TPB, HH, 1);       // 5 x 1080
    dim3 blkn(128, 1, 1);
    dim3 grdn(WW / 4 / 128 + 1, HH, 1);  // 4 x 1080
    int  grdzd = (DB4 + 255) / 256;      // dbuf zero blocks
    int  grdza = (HWN + 255) / 256;      // acc zero blocks

    for (int b = 0; b < BB; b++) {
        cudaStream_t st = (b == 0) ? main_s : s_side[b - 1];
        if (b != 0) cudaStreamWaitEvent(st, e_fork, 0);

        const float4* flow_b = (const float4*)(flow + (size_t)b * HWN * 2);
        const float*  im0_b  = im0 + (size_t)b * CC * HWN;
        float*        out_b  = out + (size_t)b * CC * HWN;
        int*          dbuf_b = dbuf + (size_t)b * HWN;
        float4*       acc_b  = acc  + (size_t)b * HWN;

        // Head exposes only the 2MB dbuf zero; acc zero hides under the
        // other streams' atomic phases between scatter and splat.
        zero_dbuf_kernel<<<grdzd, 256, 0, st>>>((int4*)dbuf_b);
        scatter_max_kernel<<<grd, blk, 0, st>>>(flow_b, dbuf_b);
        zero_acc_kernel<<<grdza, 256, 0, st>>>(acc_b);
        splat_kernel<<<grd, blk, 0, st>>>(im0_b, flow_b, dbuf_b, acc_b);
        normalize_kernel<<<grdn, blkn, 0, st>>>(acc_b, out_b);

        if (b != 0) cudaEventRecord(e_join[b - 1], st);
    }
    for (int i = 0; i < BB - 1; i++)
        cudaStreamWaitEvent(main_s, e_join[i], 0);
}